// round 11
// baseline (speedup 1.0000x reference)
#include <cuda_runtime.h>
#include <cuda_fp16.h>
#include <mma.h>
#include <math.h>

using namespace nvcuda;

#define NN 100000
#define EE 1600000
#define SCAN_B 512
#define NB ((NN + SCAN_B - 1) / SCAN_B)

struct __align__(8) Edge { int s; float w; };

// ---------------- scratch (alloc-free: __device__ globals) ----------------
__device__ int    g_is64;
__device__ int    g_deg[NN];          // raw in-degree (no self-loop)
__device__ int    g_cnt[NN];
__device__ int    g_off[NN];
__device__ int    g_cur[NN];
__device__ int    g_bsum[NB];
__device__ int    g_bpre[NB];
__device__ float  g_dinv[NN];
__device__ float  g_selfw[NN];
__device__ Edge   g_csr[EE];
__device__ __half g_bufT[(size_t)(NN + 128) * 128];  // GEMM out (row-padded for tile stores)
__device__ __half g_bufOh[(size_t)NN * 128];         // activations (gather out)

// ---------------- detect edge dtype ----------------
__global__ void k_detect(const void* __restrict__ ei) {
    if (threadIdx.x == 0) {
        const int* w = (const int*)ei;
        int nz = 0;
        for (int k = 1; k < 256; k += 2) nz += (w[k] != 0);
        g_is64 = (nz == 0) ? 1 : 0;
    }
}

__device__ __forceinline__ int edge_at(const void* __restrict__ ei, long long i) {
    if (g_is64) return (int)((const long long*)ei)[i];
    return ((const int*)ei)[i];
}

__global__ void k_count_deg(const void* __restrict__ ei) {
    int i = blockIdx.x * blockDim.x + threadIdx.x;
    if (i < EE) atomicAdd(&g_deg[edge_at(ei, (long long)EE + i)], 1);
}

// ---------------- dinv/selfw/cnt fused with local scan ----------------
__global__ void k_dinv_scan() {
    __shared__ int sm[SCAN_B];
    int v = blockIdx.x * SCAN_B + threadIdx.x;
    int c = 0;
    if (v < NN) {
        c = g_deg[v];                       // in-edges (CSR entries)
        float dv = rsqrtf((float)(c + 1));  // self-loop included in degree
        g_dinv[v] = dv;
        g_selfw[v] = dv * dv;
        g_cnt[v] = c;
    }
    sm[threadIdx.x] = c;
    __syncthreads();
    for (int off = 1; off < SCAN_B; off <<= 1) {
        int y = (threadIdx.x >= off) ? sm[threadIdx.x - off] : 0;
        __syncthreads();
        sm[threadIdx.x] += y;
        __syncthreads();
    }
    if (v < NN) g_off[v] = sm[threadIdx.x] - c;
    if (threadIdx.x == SCAN_B - 1) g_bsum[blockIdx.x] = sm[SCAN_B - 1];
}

// parallel scan over the NB block sums (NB=196 <= 256)
__global__ void k_scan_bsum_par() {
    __shared__ int sm[256];
    int i = threadIdx.x;
    int v = (i < NB) ? g_bsum[i] : 0;
    sm[i] = v;
    __syncthreads();
    for (int off = 1; off < 256; off <<= 1) {
        int y = (i >= off) ? sm[i - off] : 0;
        __syncthreads();
        sm[i] += y;
        __syncthreads();
    }
    if (i < NB) g_bpre[i] = sm[i] - v;  // exclusive prefix
}

__global__ void k_scan_add() {
    int v = blockIdx.x * blockDim.x + threadIdx.x;
    if (v < NN) {
        g_off[v] += g_bpre[v / SCAN_B];
        g_cur[v] = 0;
    }
}

__global__ void k_build_csr(const void* __restrict__ ei) {
    int e = blockIdx.x * blockDim.x + threadIdx.x;
    if (e >= EE) return;
    int s = edge_at(ei, e);
    int d = edge_at(ei, (long long)EE + e);
    Edge ed;
    ed.s = s;
    ed.w = g_dinv[s] * g_dinv[d];
    int pos = g_off[d] + atomicAdd(&g_cur[d], 1);
    g_csr[pos] = ed;
}

// ---------------- tensor-core GEMM: 512 threads, 128 rows x O cols ---------
template <int K, int O, bool IN_HALF>
__global__ __launch_bounds__(512) void wgemm_kernel(const void* __restrict__ Xv,
                                                    const float* __restrict__ W,
                                                    __half* __restrict__ out, int n) {
    constexpr int LDA = K + 8;
    constexpr int LDB = O + 8;
    constexpr int NT = O / 32;
    extern __shared__ char smraw[];
    __half* Xs = (__half*)smraw;                 // 128 x LDA
    __half* Ws = ((__half*)smraw) + 128 * LDA;   // K x LDB

    int tid = threadIdx.x;
    int warp = tid >> 5;
    int rstrip = warp >> 1;
    int chalf = warp & 1;
    int row0 = blockIdx.x * 128;

    for (int i = tid * 8; i < 128 * K; i += 512 * 8) {
        int r = i / K, c = i % K;
        uint4 pk = make_uint4(0u, 0u, 0u, 0u);
        if (row0 + r < n) {
            if constexpr (IN_HALF) {
                pk = *(const uint4*)&((const __half*)Xv)[(size_t)(row0 + r) * K + c];
            } else {
                const float* Xf = (const float*)Xv;
                float4 a = *(const float4*)&Xf[(size_t)(row0 + r) * K + c];
                float4 b = *(const float4*)&Xf[(size_t)(row0 + r) * K + c + 4];
                __half2* h = (__half2*)&pk;
                h[0] = __floats2half2_rn(a.x, a.y);
                h[1] = __floats2half2_rn(a.z, a.w);
                h[2] = __floats2half2_rn(b.x, b.y);
                h[3] = __floats2half2_rn(b.z, b.w);
            }
        }
        *(uint4*)&Xs[r * LDA + c] = pk;
    }
    for (int i = tid * 4; i < K * O; i += 512 * 4) {
        int k = i / O, c = i % O;
        float4 wv = *(const float4*)&W[(size_t)k * O + c];
        uint2 pk;
        ((__half2*)&pk)[0] = __floats2half2_rn(wv.x, wv.y);
        ((__half2*)&pk)[1] = __floats2half2_rn(wv.z, wv.w);
        *(uint2*)&Ws[k * LDB + c] = pk;
    }
    __syncthreads();

    wmma::fragment<wmma::accumulator, 16, 16, 16, float> acc[NT];
#pragma unroll
    for (int t = 0; t < NT; t++) wmma::fill_fragment(acc[t], 0.0f);

#pragma unroll
    for (int k0 = 0; k0 < K; k0 += 16) {
        wmma::fragment<wmma::matrix_a, 16, 16, 16, __half, wmma::row_major> a;
        wmma::load_matrix_sync(a, &Xs[rstrip * 16 * LDA + k0], LDA);
#pragma unroll
        for (int t = 0; t < NT; t++) {
            wmma::fragment<wmma::matrix_b, 16, 16, 16, __half, wmma::row_major> b;
            wmma::load_matrix_sync(b, &Ws[k0 * LDB + chalf * (O / 2) + t * 16], LDB);
            wmma::mma_sync(acc[t], a, b, acc[t]);
        }
    }

#pragma unroll
    for (int t = 0; t < NT; t++) {
        wmma::fragment<wmma::accumulator, 16, 16, 16, __half> h;
#pragma unroll
        for (int e2 = 0; e2 < h.num_elements; e2++) h.x[e2] = __float2half(acc[t].x[e2]);
        wmma::store_matrix_sync(&out[(size_t)(row0 + rstrip * 16) * O + chalf * (O / 2) + t * 16],
                                h, O, wmma::mem_row_major);
    }
}

// ---------------- warp-per-node CSR gather (no divergence waste) ----------
// Lane owns PL = F/32 halves. Edge load is a warp-broadcast LDG.64.
template <int F>
__global__ void gather_kernel(const float* __restrict__ bias, __half* __restrict__ O, int n) {
    constexpr int PL = F / 32;   // halves per lane: 4 (F=128) or 2 (F=64)
    int w = (blockIdx.x * blockDim.x + threadIdx.x) >> 5;
    int lane = threadIdx.x & 31;
    if (w >= n) return;
    const __half* T = g_bufT;
    size_t fo = (size_t)lane * PL;

    float acc[PL];
    {
        float sw = g_selfw[w];
        if constexpr (PL == 4) {
            uint2 r = *(const uint2*)&T[(size_t)w * F + fo];
            const __half2* h = (const __half2*)&r;
            float2 f0 = __half22float2(h[0]), f1 = __half22float2(h[1]);
            acc[0] = sw * f0.x; acc[1] = sw * f0.y;
            acc[2] = sw * f1.x; acc[3] = sw * f1.y;
        } else {
            unsigned r = *(const unsigned*)&T[(size_t)w * F + fo];
            float2 f0 = __half22float2(*(const __half2*)&r);
            acc[0] = sw * f0.x; acc[1] = sw * f0.y;
        }
    }

    int beg = g_off[w];
    int cnt = g_cnt[w];
#pragma unroll 4
    for (int i = 0; i < cnt; i++) {
        Edge e = g_csr[beg + i];   // broadcast
        if constexpr (PL == 4) {
            uint2 r = *(const uint2*)&T[(size_t)e.s * F + fo];
            const __half2* h = (const __half2*)&r;
            float2 f0 = __half22float2(h[0]), f1 = __half22float2(h[1]);
            acc[0] += e.w * f0.x; acc[1] += e.w * f0.y;
            acc[2] += e.w * f1.x; acc[3] += e.w * f1.y;
        } else {
            unsigned r = *(const unsigned*)&T[(size_t)e.s * F + fo];
            float2 f0 = __half22float2(*(const __half2*)&r);
            acc[0] += e.w * f0.x; acc[1] += e.w * f0.y;
        }
    }

    if constexpr (PL == 4) {
        float4 b = *(const float4*)&bias[fo];
        uint2 pk;
        ((__half2*)&pk)[0] = __floats2half2_rn(fmaxf(acc[0] + b.x, 0.f), fmaxf(acc[1] + b.y, 0.f));
        ((__half2*)&pk)[1] = __floats2half2_rn(fmaxf(acc[2] + b.z, 0.f), fmaxf(acc[3] + b.w, 0.f));
        *(uint2*)&O[(size_t)w * F + fo] = pk;
    } else {
        float2 b = *(const float2*)&bias[fo];
        unsigned pk;
        *(__half2*)&pk = __floats2half2_rn(fmaxf(acc[0] + b.x, 0.f), fmaxf(acc[1] + b.y, 0.f));
        *(unsigned*)&O[(size_t)w * F + fo] = pk;
    }
}

// ---------------- layer-3 gather fused with logistic head (warp-per-node) --
__global__ void gather_head_kernel(const float* __restrict__ bias,
                                   const float* __restrict__ Wl,
                                   const float* __restrict__ bl,
                                   float* __restrict__ out, int n) {
    constexpr int F = 32;
    int w = (blockIdx.x * blockDim.x + threadIdx.x) >> 5;
    int lane = threadIdx.x & 31;
    if (w >= n) return;
    const __half* T = g_bufT;

    float acc = g_selfw[w] * __half2float(T[(size_t)w * F + lane]);
    int beg = g_off[w];
    int cnt = g_cnt[w];
#pragma unroll 4
    for (int i = 0; i < cnt; i++) {
        Edge e = g_csr[beg + i];
        acc += e.w * __half2float(T[(size_t)e.s * F + lane]);
    }
    float p = fmaxf(acc + bias[lane], 0.f) * Wl[lane];
#pragma unroll
    for (int off = 16; off; off >>= 1) p += __shfl_down_sync(0xffffffffu, p, off);
    if (lane == 0) out[w] = 1.f / (1.f + __expf(-(p + bl[0])));
}

extern "C" void kernel_launch(void* const* d_in, const int* in_sizes, int n_in,
                              void* d_out, int out_size) {
    const float* x = (const float*)d_in[0];
    const void* ei = (const void*)d_in[1];
    const float* W1 = (const float*)d_in[2];
    const float* b1 = (const float*)d_in[3];
    const float* W2 = (const float*)d_in[4];
    const float* b2 = (const float*)d_in[5];
    const float* W3 = (const float*)d_in[6];
    const float* b3 = (const float*)d_in[7];
    const float* Wl = (const float*)d_in[8];
    const float* bl = (const float*)d_in[9];
    float* out = (float*)d_out;
    int n = NN;

    constexpr int SM1 = (128 * (128 + 8) + 128 * (128 + 8)) * 2;  // 69632
    constexpr int SM2 = (128 * (128 + 8) + 128 * (64 + 8)) * 2;   // 53248
    constexpr int SM3 = (128 * (64 + 8) + 64 * (32 + 8)) * 2;     // 23552
    cudaFuncSetAttribute(wgemm_kernel<128, 128, false>, cudaFuncAttributeMaxDynamicSharedMemorySize, SM1);
    cudaFuncSetAttribute(wgemm_kernel<128, 64, true>, cudaFuncAttributeMaxDynamicSharedMemorySize, SM2);
    cudaFuncSetAttribute(wgemm_kernel<64, 32, true>, cudaFuncAttributeMaxDynamicSharedMemorySize, SM3);

    __half* T;
    __half* Oh;
    int* degp;
    cudaGetSymbolAddress((void**)&T, g_bufT);
    cudaGetSymbolAddress((void**)&Oh, g_bufOh);
    cudaGetSymbolAddress((void**)&degp, g_deg);

    // one-time host objects (no device memory)
    static cudaStream_t s2 = nullptr;
    static cudaEvent_t evFork = nullptr, evJoin = nullptr;
    if (s2 == nullptr) {
        cudaStreamCreateWithFlags(&s2, cudaStreamNonBlocking);
        cudaEventCreateWithFlags(&evFork, cudaEventDisableTiming);
        cudaEventCreateWithFlags(&evJoin, cudaEventDisableTiming);
    }

    // ---- fork: layer-1 GEMM on s2 (depends only on x, W1) ----
    cudaEventRecord(evFork, 0);
    cudaStreamWaitEvent(s2, evFork, 0);
    wgemm_kernel<128, 128, false><<<(n + 127) / 128, 512, SM1, s2>>>(x, W1, T, n);
    cudaEventRecord(evJoin, s2);

    // ---- preprocessing chain on the capture stream ----
    cudaMemsetAsync(degp, 0, NN * sizeof(int), 0);
    k_detect<<<1, 32>>>(ei);
    k_count_deg<<<(EE + 255) / 256, 256>>>(ei);
    k_dinv_scan<<<NB, SCAN_B>>>();
    k_scan_bsum_par<<<1, 256>>>();
    k_scan_add<<<(NN + 255) / 256, 256>>>();
    k_build_csr<<<(EE + 255) / 256, 256>>>(ei);

    // ---- join: gather1 needs both gemm1 (T) and the CSR ----
    cudaStreamWaitEvent(0, evJoin, 0);
    gather_kernel<128><<<(n * 32 + 255) / 256, 256>>>(b1, Oh, n);

    // --- layer 2: 128 -> 64 ---
    wgemm_kernel<128, 64, true><<<(n + 127) / 128, 512, SM2>>>(Oh, W2, T, n);
    gather_kernel<64><<<(n * 32 + 255) / 256, 256>>>(b2, Oh, n);

    // --- layer 3: 64 -> 32 + head ---
    wgemm_kernel<64, 32, true><<<(n + 127) / 128, 512, SM3>>>(Oh, W3, T, n);
    gather_head_kernel<<<(n * 32 + 255) / 256, 256>>>(b3, Wl, bl, out, n);
}

// round 12
// speedup vs baseline: 1.0599x; 1.0599x over previous
#include <cuda_runtime.h>
#include <cuda_fp16.h>
#include <mma.h>
#include <math.h>

using namespace nvcuda;

#define NN 100000
#define EE 1600000
#define SCAN_B 512
#define NB ((NN + SCAN_B - 1) / SCAN_B)
#define H0 50048                      // 391 gemm tiles of 128 rows
#define GB_ALL (((NN) + 127) / 128)   // 782
#define GB_H0 (H0 / 128)              // 391

struct __align__(8) Edge { int s; float w; };

// ---------------- scratch (alloc-free: __device__ globals) ----------------
__device__ int    g_is64;
__device__ int    g_deg[NN];          // raw in-degree (no self-loop)
__device__ int    g_cnt[NN];
__device__ int    g_off[NN];
__device__ int    g_cur[NN];
__device__ int    g_bsum[NB];
__device__ int    g_bpre[NB];
__device__ float  g_dinv[NN];
__device__ float  g_selfw[NN];
__device__ Edge   g_csr[EE];
__device__ __half g_bufT[(size_t)(NN + 128) * 128];  // GEMM out (row-padded for tile stores)
__device__ __half g_bufOh[(size_t)NN * 128];         // activations (gather out)

// ---------------- detect edge dtype ----------------
__global__ void k_detect(const void* __restrict__ ei) {
    if (threadIdx.x == 0) {
        const int* w = (const int*)ei;
        int nz = 0;
        for (int k = 1; k < 256; k += 2) nz += (w[k] != 0);
        g_is64 = (nz == 0) ? 1 : 0;
    }
}

__device__ __forceinline__ int edge_at(const void* __restrict__ ei, long long i) {
    if (g_is64) return (int)((const long long*)ei)[i];
    return ((const int*)ei)[i];
}

__global__ void k_count_deg(const void* __restrict__ ei) {
    int i = blockIdx.x * blockDim.x + threadIdx.x;
    if (i < EE) atomicAdd(&g_deg[edge_at(ei, (long long)EE + i)], 1);
}

// ---------------- dinv/selfw/cnt fused with local scan ----------------
__global__ void k_dinv_scan() {
    __shared__ int sm[SCAN_B];
    int v = blockIdx.x * SCAN_B + threadIdx.x;
    int c = 0;
    if (v < NN) {
        c = g_deg[v];
        float dv = rsqrtf((float)(c + 1));  // + self-loop
        g_dinv[v] = dv;
        g_selfw[v] = dv * dv;
        g_cnt[v] = c;
    }
    sm[threadIdx.x] = c;
    __syncthreads();
    for (int off = 1; off < SCAN_B; off <<= 1) {
        int y = (threadIdx.x >= off) ? sm[threadIdx.x - off] : 0;
        __syncthreads();
        sm[threadIdx.x] += y;
        __syncthreads();
    }
    if (v < NN) g_off[v] = sm[threadIdx.x] - c;
    if (threadIdx.x == SCAN_B - 1) g_bsum[blockIdx.x] = sm[SCAN_B - 1];
}

__global__ void k_scan_bsum_par() {
    __shared__ int sm[256];
    int i = threadIdx.x;
    int v = (i < NB) ? g_bsum[i] : 0;
    sm[i] = v;
    __syncthreads();
    for (int off = 1; off < 256; off <<= 1) {
        int y = (i >= off) ? sm[i - off] : 0;
        __syncthreads();
        sm[i] += y;
        __syncthreads();
    }
    if (i < NB) g_bpre[i] = sm[i] - v;
}

__global__ void k_scan_add() {
    int v = blockIdx.x * blockDim.x + threadIdx.x;
    if (v < NN) {
        g_off[v] += g_bpre[v / SCAN_B];
        g_cur[v] = 0;
    }
}

__global__ void k_build_csr(const void* __restrict__ ei) {
    int e = blockIdx.x * blockDim.x + threadIdx.x;
    if (e >= EE) return;
    int s = edge_at(ei, e);
    int d = edge_at(ei, (long long)EE + e);
    Edge ed;
    ed.s = s;
    ed.w = g_dinv[s] * g_dinv[d];
    int pos = g_off[d] + atomicAdd(&g_cur[d], 1);
    g_csr[pos] = ed;
}

// ---------------- tensor-core GEMM: 512 threads, 128 rows x O cols ---------
// bx0 = tile offset (for half launches).
template <int K, int O, bool IN_HALF>
__global__ __launch_bounds__(512) void wgemm_kernel(const void* __restrict__ Xv,
                                                    const float* __restrict__ W,
                                                    __half* __restrict__ out, int n, int bx0) {
    constexpr int LDA = K + 8;
    constexpr int LDB = O + 8;
    constexpr int NT = O / 32;
    extern __shared__ char smraw[];
    __half* Xs = (__half*)smraw;                 // 128 x LDA
    __half* Ws = ((__half*)smraw) + 128 * LDA;   // K x LDB

    int tid = threadIdx.x;
    int warp = tid >> 5;
    int rstrip = warp >> 1;
    int chalf = warp & 1;
    int row0 = (blockIdx.x + bx0) * 128;

    for (int i = tid * 8; i < 128 * K; i += 512 * 8) {
        int r = i / K, c = i % K;
        uint4 pk = make_uint4(0u, 0u, 0u, 0u);
        if (row0 + r < n) {
            if constexpr (IN_HALF) {
                pk = *(const uint4*)&((const __half*)Xv)[(size_t)(row0 + r) * K + c];
            } else {
                const float* Xf = (const float*)Xv;
                float4 a = *(const float4*)&Xf[(size_t)(row0 + r) * K + c];
                float4 b = *(const float4*)&Xf[(size_t)(row0 + r) * K + c + 4];
                __half2* h = (__half2*)&pk;
                h[0] = __floats2half2_rn(a.x, a.y);
                h[1] = __floats2half2_rn(a.z, a.w);
                h[2] = __floats2half2_rn(b.x, b.y);
                h[3] = __floats2half2_rn(b.z, b.w);
            }
        }
        *(uint4*)&Xs[r * LDA + c] = pk;
    }
    for (int i = tid * 4; i < K * O; i += 512 * 4) {
        int k = i / O, c = i % O;
        float4 wv = *(const float4*)&W[(size_t)k * O + c];
        uint2 pk;
        ((__half2*)&pk)[0] = __floats2half2_rn(wv.x, wv.y);
        ((__half2*)&pk)[1] = __floats2half2_rn(wv.z, wv.w);
        *(uint2*)&Ws[k * LDB + c] = pk;
    }
    __syncthreads();

    wmma::fragment<wmma::accumulator, 16, 16, 16, float> acc[NT];
#pragma unroll
    for (int t = 0; t < NT; t++) wmma::fill_fragment(acc[t], 0.0f);

#pragma unroll
    for (int k0 = 0; k0 < K; k0 += 16) {
        wmma::fragment<wmma::matrix_a, 16, 16, 16, __half, wmma::row_major> a;
        wmma::load_matrix_sync(a, &Xs[rstrip * 16 * LDA + k0], LDA);
#pragma unroll
        for (int t = 0; t < NT; t++) {
            wmma::fragment<wmma::matrix_b, 16, 16, 16, __half, wmma::row_major> b;
            wmma::load_matrix_sync(b, &Ws[k0 * LDB + chalf * (O / 2) + t * 16], LDB);
            wmma::mma_sync(acc[t], a, b, acc[t]);
        }
    }

#pragma unroll
    for (int t = 0; t < NT; t++) {
        wmma::fragment<wmma::accumulator, 16, 16, 16, __half> h;
#pragma unroll
        for (int e2 = 0; e2 < h.num_elements; e2++) h.x[e2] = __float2half(acc[t].x[e2]);
        wmma::store_matrix_sync(&out[(size_t)(row0 + rstrip * 16) * O + chalf * (O / 2) + t * 16],
                                h, O, wmma::mem_row_major);
    }
}

// ---------------- CSR gather (fp16 in, fp32 acc, fp16 out), node range -----
template <int F>
__global__ void gather_kernel(const float* __restrict__ bias, __half* __restrict__ O,
                              int v0, int vend) {
    constexpr int G = F / 8;
    int t = blockIdx.x * blockDim.x + threadIdx.x;
    int v = v0 + t / G;
    int q = t % G;
    if (v >= vend) return;
    const __half* T = g_bufT;
    size_t fo = (size_t)q * 8;

    float acc[8];
    {
        float sw = g_selfw[v];
        uint4 r = *(const uint4*)&T[(size_t)v * F + fo];
        const __half2* h = (const __half2*)&r;
#pragma unroll
        for (int p = 0; p < 4; p++) {
            float2 f = __half22float2(h[p]);
            acc[2 * p] = sw * f.x;
            acc[2 * p + 1] = sw * f.y;
        }
    }

    int beg = g_off[v];
    int cnt = g_cnt[v];
#pragma unroll 4
    for (int i = 0; i < cnt; i++) {
        Edge e = g_csr[beg + i];
        uint4 r = *(const uint4*)&T[(size_t)e.s * F + fo];
        const __half2* h = (const __half2*)&r;
#pragma unroll
        for (int p = 0; p < 4; p++) {
            float2 f = __half22float2(h[p]);
            acc[2 * p] += e.w * f.x;
            acc[2 * p + 1] += e.w * f.y;
        }
    }

    float4 b0 = *(const float4*)&bias[fo];
    float4 b1 = *(const float4*)&bias[fo + 4];
    uint4 pk;
    ((__half2*)&pk)[0] = __floats2half2_rn(fmaxf(acc[0] + b0.x, 0.f), fmaxf(acc[1] + b0.y, 0.f));
    ((__half2*)&pk)[1] = __floats2half2_rn(fmaxf(acc[2] + b0.z, 0.f), fmaxf(acc[3] + b0.w, 0.f));
    ((__half2*)&pk)[2] = __floats2half2_rn(fmaxf(acc[4] + b1.x, 0.f), fmaxf(acc[5] + b1.y, 0.f));
    ((__half2*)&pk)[3] = __floats2half2_rn(fmaxf(acc[6] + b1.z, 0.f), fmaxf(acc[7] + b1.w, 0.f));
    *(uint4*)&O[(size_t)v * F + fo] = pk;
}

// ---------------- layer-3 gather fused with logistic head ----------------
__global__ void gather_head_kernel(const float* __restrict__ bias,
                                   const float* __restrict__ Wl,
                                   const float* __restrict__ bl,
                                   float* __restrict__ out, int n) {
    constexpr int F = 32, G = 4;
    int t = blockIdx.x * blockDim.x + threadIdx.x;
    int v = t / G;
    int q = t % G;
    if (v >= n) return;
    const __half* T = g_bufT;
    size_t fo = (size_t)q * 8;

    float acc[8];
    {
        float sw = g_selfw[v];
        uint4 r = *(const uint4*)&T[(size_t)v * F + fo];
        const __half2* h = (const __half2*)&r;
#pragma unroll
        for (int p = 0; p < 4; p++) {
            float2 f = __half22float2(h[p]);
            acc[2 * p] = sw * f.x;
            acc[2 * p + 1] = sw * f.y;
        }
    }

    int beg = g_off[v];
    int cnt = g_cnt[v];
#pragma unroll 4
    for (int i = 0; i < cnt; i++) {
        Edge e = g_csr[beg + i];
        uint4 r = *(const uint4*)&T[(size_t)e.s * F + fo];
        const __half2* h = (const __half2*)&r;
#pragma unroll
        for (int p = 0; p < 4; p++) {
            float2 f = __half22float2(h[p]);
            acc[2 * p] += e.w * f.x;
            acc[2 * p + 1] += e.w * f.y;
        }
    }

    float4 b0 = *(const float4*)&bias[fo];
    float4 b1 = *(const float4*)&bias[fo + 4];
    float4 w0 = *(const float4*)&Wl[fo];
    float4 w1 = *(const float4*)&Wl[fo + 4];
    float p = fmaxf(acc[0] + b0.x, 0.f) * w0.x + fmaxf(acc[1] + b0.y, 0.f) * w0.y +
              fmaxf(acc[2] + b0.z, 0.f) * w0.z + fmaxf(acc[3] + b0.w, 0.f) * w0.w +
              fmaxf(acc[4] + b1.x, 0.f) * w1.x + fmaxf(acc[5] + b1.y, 0.f) * w1.y +
              fmaxf(acc[6] + b1.z, 0.f) * w1.z + fmaxf(acc[7] + b1.w, 0.f) * w1.w;
#pragma unroll
    for (int off = 2; off; off >>= 1) p += __shfl_down_sync(0xffffffffu, p, off, G);
    if (q == 0) out[v] = 1.f / (1.f + __expf(-(p + bl[0])));
}

extern "C" void kernel_launch(void* const* d_in, const int* in_sizes, int n_in,
                              void* d_out, int out_size) {
    const float* x = (const float*)d_in[0];
    const void* ei = (const void*)d_in[1];
    const float* W1 = (const float*)d_in[2];
    const float* b1 = (const float*)d_in[3];
    const float* W2 = (const float*)d_in[4];
    const float* b2 = (const float*)d_in[5];
    const float* W3 = (const float*)d_in[6];
    const float* b3 = (const float*)d_in[7];
    const float* Wl = (const float*)d_in[8];
    const float* bl = (const float*)d_in[9];
    float* out = (float*)d_out;
    int n = NN;

    constexpr int SM1 = (128 * (128 + 8) + 128 * (128 + 8)) * 2;  // 69632
    constexpr int SM2 = (128 * (128 + 8) + 128 * (64 + 8)) * 2;   // 53248
    constexpr int SM3 = (128 * (64 + 8) + 64 * (32 + 8)) * 2;     // 23552
    cudaFuncSetAttribute(wgemm_kernel<128, 128, false>, cudaFuncAttributeMaxDynamicSharedMemorySize, SM1);
    cudaFuncSetAttribute(wgemm_kernel<128, 64, true>, cudaFuncAttributeMaxDynamicSharedMemorySize, SM2);
    cudaFuncSetAttribute(wgemm_kernel<64, 32, true>, cudaFuncAttributeMaxDynamicSharedMemorySize, SM3);

    __half* T;
    __half* Oh;
    int* degp;
    cudaGetSymbolAddress((void**)&T, g_bufT);
    cudaGetSymbolAddress((void**)&Oh, g_bufOh);
    cudaGetSymbolAddress((void**)&degp, g_deg);

    // one-time host objects (no device memory)
    static cudaStream_t s2 = nullptr;
    static cudaEvent_t evFork = nullptr, evJ1 = nullptr, evG1 = nullptr,
                       evJ2 = nullptr, evG2 = nullptr, evJ3 = nullptr;
    if (s2 == nullptr) {
        cudaStreamCreateWithFlags(&s2, cudaStreamNonBlocking);
        cudaEventCreateWithFlags(&evFork, cudaEventDisableTiming);
        cudaEventCreateWithFlags(&evJ1, cudaEventDisableTiming);
        cudaEventCreateWithFlags(&evG1, cudaEventDisableTiming);
        cudaEventCreateWithFlags(&evJ2, cudaEventDisableTiming);
        cudaEventCreateWithFlags(&evG2, cudaEventDisableTiming);
        cudaEventCreateWithFlags(&evJ3, cudaEventDisableTiming);
    }

    // ---- fork: layer-1 GEMM on s2 (depends only on x, W1) ----
    cudaEventRecord(evFork, 0);
    cudaStreamWaitEvent(s2, evFork, 0);
    wgemm_kernel<128, 128, false><<<GB_ALL, 512, SM1, s2>>>(x, W1, T, n, 0);
    cudaEventRecord(evJ1, s2);

    // ---- preprocessing chain on the capture stream ----
    cudaMemsetAsync(degp, 0, NN * sizeof(int), 0);
    k_detect<<<1, 32>>>(ei);
    k_count_deg<<<(EE + 255) / 256, 256>>>(ei);
    k_dinv_scan<<<NB, SCAN_B>>>();
    k_scan_bsum_par<<<1, 256>>>();
    k_scan_add<<<(NN + 255) / 256, 256>>>();
    k_build_csr<<<(EE + 255) / 256, 256>>>(ei);

    // ---- layer 1 gather, pipelined with layer-2 GEMM ----
    cudaStreamWaitEvent(0, evJ1, 0);
    gather_kernel<128><<<(H0 * 16 + 255) / 256, 256>>>(b1, Oh, 0, H0);
    cudaEventRecord(evG1, 0);
    gather_kernel<128><<<((n - H0) * 16 + 255) / 256, 256>>>(b1, Oh, H0, n);

    cudaStreamWaitEvent(s2, evG1, 0);
    wgemm_kernel<128, 64, true><<<GB_H0, 512, SM2, s2>>>(Oh, W2, T, n, 0);        // rows [0,H0)
    cudaEventRecord(evJ2, s2);
    wgemm_kernel<128, 64, true><<<GB_ALL - GB_H0, 512, SM2>>>(Oh, W2, T, n, GB_H0);  // rest

    // ---- layer 2 gather, pipelined with layer-3 GEMM ----
    cudaStreamWaitEvent(0, evJ2, 0);
    gather_kernel<64><<<(H0 * 8 + 255) / 256, 256>>>(b2, Oh, 0, H0);
    cudaEventRecord(evG2, 0);
    gather_kernel<64><<<((n - H0) * 8 + 255) / 256, 256>>>(b2, Oh, H0, n);

    cudaStreamWaitEvent(s2, evG2, 0);
    wgemm_kernel<64, 32, true><<<GB_H0, 512, SM3, s2>>>(Oh, W3, T, n, 0);
    cudaEventRecord(evJ3, s2);
    wgemm_kernel<64, 32, true><<<GB_ALL - GB_H0, 512, SM3>>>(Oh, W3, T, n, GB_H0);

    // ---- head (needs full T from layer 3) ----
    cudaStreamWaitEvent(0, evJ3, 0);
    gather_head_kernel<<<(n * 4 + 255) / 256, 256>>>(b3, Wl, bl, out, n);
}

// round 13
// speedup vs baseline: 1.0748x; 1.0141x over previous
#include <cuda_runtime.h>
#include <cuda_fp16.h>
#include <mma.h>
#include <math.h>

using namespace nvcuda;

#define NN 100000
#define EE 1600000
#define SCAN_B 512
#define NB ((NN + SCAN_B - 1) / SCAN_B)

struct __align__(8) Edge { int s; float w; };

// ---------------- scratch (alloc-free: __device__ globals) ----------------
__device__ int    g_is64;
__device__ int    g_deg[NN];          // raw in-degree (no self-loop)
__device__ int    g_cnt[NN];
__device__ int    g_off[NN];          // LOCAL scan offsets (block prefix added at use)
__device__ int    g_cur[NN];
__device__ int    g_bsum[NB];
__device__ int    g_bpre[NB];
__device__ float  g_dinv[NN];
__device__ float  g_selfw[NN];
__device__ Edge   g_csr[EE];
__device__ __half g_bufT[(size_t)(NN + 128) * 128];  // GEMM out (row-padded for tile stores)
__device__ __half g_bufOh[(size_t)NN * 128];         // activations (gather out)

// ---------------- zero degrees + detect edge dtype (one kernel) ----------
__global__ void k_pre0(const void* __restrict__ ei) {
    int i = blockIdx.x * blockDim.x + threadIdx.x;
    if (i < NN) g_deg[i] = 0;
    if (i == 0) {
        const int* w = (const int*)ei;
        int nz = 0;
        for (int k = 1; k < 256; k += 2) nz += (w[k] != 0);
        g_is64 = (nz == 0) ? 1 : 0;
    }
}

__device__ __forceinline__ int edge_at(const void* __restrict__ ei, long long i) {
    if (g_is64) return (int)((const long long*)ei)[i];
    return ((const int*)ei)[i];
}

__global__ void k_count_deg(const void* __restrict__ ei) {
    int i = blockIdx.x * blockDim.x + threadIdx.x;
    if (i < EE) atomicAdd(&g_deg[edge_at(ei, (long long)EE + i)], 1);
}

// ---------------- dinv/selfw/cnt/cur + local scan (fused) ----------------
__global__ void k_dinv_scan() {
    __shared__ int sm[SCAN_B];
    int v = blockIdx.x * SCAN_B + threadIdx.x;
    int c = 0;
    if (v < NN) {
        c = g_deg[v];
        float dv = rsqrtf((float)(c + 1));  // + self-loop
        g_dinv[v] = dv;
        g_selfw[v] = dv * dv;
        g_cnt[v] = c;
        g_cur[v] = 0;
    }
    sm[threadIdx.x] = c;
    __syncthreads();
    for (int off = 1; off < SCAN_B; off <<= 1) {
        int y = (threadIdx.x >= off) ? sm[threadIdx.x - off] : 0;
        __syncthreads();
        sm[threadIdx.x] += y;
        __syncthreads();
    }
    if (v < NN) g_off[v] = sm[threadIdx.x] - c;  // local exclusive offset
    if (threadIdx.x == SCAN_B - 1) g_bsum[blockIdx.x] = sm[SCAN_B - 1];
}

// parallel scan over the NB block sums (NB=196 <= 256)
__global__ void k_scan_bsum_par() {
    __shared__ int sm[256];
    int i = threadIdx.x;
    int v = (i < NB) ? g_bsum[i] : 0;
    sm[i] = v;
    __syncthreads();
    for (int off = 1; off < 256; off <<= 1) {
        int y = (i >= off) ? sm[i - off] : 0;
        __syncthreads();
        sm[i] += y;
        __syncthreads();
    }
    if (i < NB) g_bpre[i] = sm[i] - v;  // exclusive prefix of block sums
}

__device__ __forceinline__ int node_beg(int v) { return g_off[v] + g_bpre[v >> 9]; }

__global__ void k_build_csr(const void* __restrict__ ei) {
    int e = blockIdx.x * blockDim.x + threadIdx.x;
    if (e >= EE) return;
    int s = edge_at(ei, e);
    int d = edge_at(ei, (long long)EE + e);
    Edge ed;
    ed.s = s;
    ed.w = g_dinv[s] * g_dinv[d];
    int pos = node_beg(d) + atomicAdd(&g_cur[d], 1);
    g_csr[pos] = ed;
}

// ---------------- tensor-core GEMM: 512 threads, 128 rows x O cols ---------
template <int K, int O, bool IN_HALF>
__global__ __launch_bounds__(512) void wgemm_kernel(const void* __restrict__ Xv,
                                                    const float* __restrict__ W,
                                                    __half* __restrict__ out, int n) {
    constexpr int LDA = K + 8;
    constexpr int LDB = O + 8;
    constexpr int NT = O / 32;
    extern __shared__ char smraw[];
    __half* Xs = (__half*)smraw;                 // 128 x LDA
    __half* Ws = ((__half*)smraw) + 128 * LDA;   // K x LDB

    int tid = threadIdx.x;
    int warp = tid >> 5;
    int rstrip = warp >> 1;
    int chalf = warp & 1;
    int row0 = blockIdx.x * 128;

    for (int i = tid * 8; i < 128 * K; i += 512 * 8) {
        int r = i / K, c = i % K;
        uint4 pk = make_uint4(0u, 0u, 0u, 0u);
        if (row0 + r < n) {
            if constexpr (IN_HALF) {
                pk = *(const uint4*)&((const __half*)Xv)[(size_t)(row0 + r) * K + c];
            } else {
                const float* Xf = (const float*)Xv;
                float4 a = *(const float4*)&Xf[(size_t)(row0 + r) * K + c];
                float4 b = *(const float4*)&Xf[(size_t)(row0 + r) * K + c + 4];
                __half2* h = (__half2*)&pk;
                h[0] = __floats2half2_rn(a.x, a.y);
                h[1] = __floats2half2_rn(a.z, a.w);
                h[2] = __floats2half2_rn(b.x, b.y);
                h[3] = __floats2half2_rn(b.z, b.w);
            }
        }
        *(uint4*)&Xs[r * LDA + c] = pk;
    }
    for (int i = tid * 4; i < K * O; i += 512 * 4) {
        int k = i / O, c = i % O;
        float4 wv = *(const float4*)&W[(size_t)k * O + c];
        uint2 pk;
        ((__half2*)&pk)[0] = __floats2half2_rn(wv.x, wv.y);
        ((__half2*)&pk)[1] = __floats2half2_rn(wv.z, wv.w);
        *(uint2*)&Ws[k * LDB + c] = pk;
    }
    __syncthreads();

    wmma::fragment<wmma::accumulator, 16, 16, 16, float> acc[NT];
#pragma unroll
    for (int t = 0; t < NT; t++) wmma::fill_fragment(acc[t], 0.0f);

#pragma unroll
    for (int k0 = 0; k0 < K; k0 += 16) {
        wmma::fragment<wmma::matrix_a, 16, 16, 16, __half, wmma::row_major> a;
        wmma::load_matrix_sync(a, &Xs[rstrip * 16 * LDA + k0], LDA);
#pragma unroll
        for (int t = 0; t < NT; t++) {
            wmma::fragment<wmma::matrix_b, 16, 16, 16, __half, wmma::row_major> b;
            wmma::load_matrix_sync(b, &Ws[k0 * LDB + chalf * (O / 2) + t * 16], LDB);
            wmma::mma_sync(acc[t], a, b, acc[t]);
        }
    }

#pragma unroll
    for (int t = 0; t < NT; t++) {
        wmma::fragment<wmma::accumulator, 16, 16, 16, __half> h;
#pragma unroll
        for (int e2 = 0; e2 < h.num_elements; e2++) h.x[e2] = __float2half(acc[t].x[e2]);
        wmma::store_matrix_sync(&out[(size_t)(row0 + rstrip * 16) * O + chalf * (O / 2) + t * 16],
                                h, O, wmma::mem_row_major);
    }
}

// ---------------- CSR gather (fp16 in, fp32 acc, fp16 out) ----------------
// G = F/8 lanes per node (multi-node warps keep edge-stream MLP high).
template <int F>
__global__ void gather_kernel(const float* __restrict__ bias, __half* __restrict__ O, int n) {
    constexpr int G = F / 8;
    int t = blockIdx.x * blockDim.x + threadIdx.x;
    int v = t / G;
    int q = t % G;
    if (v >= n) return;
    const __half* T = g_bufT;
    size_t fo = (size_t)q * 8;

    float acc[8];
    {
        float sw = g_selfw[v];
        uint4 r = *(const uint4*)&T[(size_t)v * F + fo];
        const __half2* h = (const __half2*)&r;
#pragma unroll
        for (int p = 0; p < 4; p++) {
            float2 f = __half22float2(h[p]);
            acc[2 * p] = sw * f.x;
            acc[2 * p + 1] = sw * f.y;
        }
    }

    int beg = node_beg(v);
    int cnt = g_cnt[v];
#pragma unroll 4
    for (int i = 0; i < cnt; i++) {
        Edge e = g_csr[beg + i];
        uint4 r = *(const uint4*)&T[(size_t)e.s * F + fo];
        const __half2* h = (const __half2*)&r;
#pragma unroll
        for (int p = 0; p < 4; p++) {
            float2 f = __half22float2(h[p]);
            acc[2 * p] += e.w * f.x;
            acc[2 * p + 1] += e.w * f.y;
        }
    }

    float4 b0 = *(const float4*)&bias[fo];
    float4 b1 = *(const float4*)&bias[fo + 4];
    uint4 pk;
    ((__half2*)&pk)[0] = __floats2half2_rn(fmaxf(acc[0] + b0.x, 0.f), fmaxf(acc[1] + b0.y, 0.f));
    ((__half2*)&pk)[1] = __floats2half2_rn(fmaxf(acc[2] + b0.z, 0.f), fmaxf(acc[3] + b0.w, 0.f));
    ((__half2*)&pk)[2] = __floats2half2_rn(fmaxf(acc[4] + b1.x, 0.f), fmaxf(acc[5] + b1.y, 0.f));
    ((__half2*)&pk)[3] = __floats2half2_rn(fmaxf(acc[6] + b1.z, 0.f), fmaxf(acc[7] + b1.w, 0.f));
    *(uint4*)&O[(size_t)v * F + fo] = pk;
}

// ---------------- layer-3 gather fused with logistic head ----------------
__global__ void gather_head_kernel(const float* __restrict__ bias,
                                   const float* __restrict__ Wl,
                                   const float* __restrict__ bl,
                                   float* __restrict__ out, int n) {
    constexpr int F = 32, G = 4;
    int t = blockIdx.x * blockDim.x + threadIdx.x;
    int v = t / G;
    int q = t % G;
    if (v >= n) return;
    const __half* T = g_bufT;
    size_t fo = (size_t)q * 8;

    float acc[8];
    {
        float sw = g_selfw[v];
        uint4 r = *(const uint4*)&T[(size_t)v * F + fo];
        const __half2* h = (const __half2*)&r;
#pragma unroll
        for (int p = 0; p < 4; p++) {
            float2 f = __half22float2(h[p]);
            acc[2 * p] = sw * f.x;
            acc[2 * p + 1] = sw * f.y;
        }
    }

    int beg = node_beg(v);
    int cnt = g_cnt[v];
#pragma unroll 4
    for (int i = 0; i < cnt; i++) {
        Edge e = g_csr[beg + i];
        uint4 r = *(const uint4*)&T[(size_t)e.s * F + fo];
        const __half2* h = (const __half2*)&r;
#pragma unroll
        for (int p = 0; p < 4; p++) {
            float2 f = __half22float2(h[p]);
            acc[2 * p] += e.w * f.x;
            acc[2 * p + 1] += e.w * f.y;
        }
    }

    float4 b0 = *(const float4*)&bias[fo];
    float4 b1 = *(const float4*)&bias[fo + 4];
    float4 w0 = *(const float4*)&Wl[fo];
    float4 w1 = *(const float4*)&Wl[fo + 4];
    float p = fmaxf(acc[0] + b0.x, 0.f) * w0.x + fmaxf(acc[1] + b0.y, 0.f) * w0.y +
              fmaxf(acc[2] + b0.z, 0.f) * w0.z + fmaxf(acc[3] + b0.w, 0.f) * w0.w +
              fmaxf(acc[4] + b1.x, 0.f) * w1.x + fmaxf(acc[5] + b1.y, 0.f) * w1.y +
              fmaxf(acc[6] + b1.z, 0.f) * w1.z + fmaxf(acc[7] + b1.w, 0.f) * w1.w;
#pragma unroll
    for (int off = 2; off; off >>= 1) p += __shfl_down_sync(0xffffffffu, p, off, G);
    if (q == 0) out[v] = 1.f / (1.f + __expf(-(p + bl[0])));
}

extern "C" void kernel_launch(void* const* d_in, const int* in_sizes, int n_in,
                              void* d_out, int out_size) {
    const float* x = (const float*)d_in[0];
    const void* ei = (const void*)d_in[1];
    const float* W1 = (const float*)d_in[2];
    const float* b1 = (const float*)d_in[3];
    const float* W2 = (const float*)d_in[4];
    const float* b2 = (const float*)d_in[5];
    const float* W3 = (const float*)d_in[6];
    const float* b3 = (const float*)d_in[7];
    const float* Wl = (const float*)d_in[8];
    const float* bl = (const float*)d_in[9];
    float* out = (float*)d_out;
    int n = NN;

    constexpr int SM1 = (128 * (128 + 8) + 128 * (128 + 8)) * 2;  // 69632
    constexpr int SM2 = (128 * (128 + 8) + 128 * (64 + 8)) * 2;   // 53248
    constexpr int SM3 = (128 * (64 + 8) + 64 * (32 + 8)) * 2;     // 23552
    cudaFuncSetAttribute(wgemm_kernel<128, 128, false>, cudaFuncAttributeMaxDynamicSharedMemorySize, SM1);
    cudaFuncSetAttribute(wgemm_kernel<128, 64, true>, cudaFuncAttributeMaxDynamicSharedMemorySize, SM2);
    cudaFuncSetAttribute(wgemm_kernel<64, 32, true>, cudaFuncAttributeMaxDynamicSharedMemorySize, SM3);

    __half* T;
    __half* Oh;
    cudaGetSymbolAddress((void**)&T, g_bufT);
    cudaGetSymbolAddress((void**)&Oh, g_bufOh);

    // one-time host objects (no device memory)
    static cudaStream_t s2 = nullptr;
    static cudaEvent_t evFork = nullptr, evJoin = nullptr;
    if (s2 == nullptr) {
        cudaStreamCreateWithFlags(&s2, cudaStreamNonBlocking);
        cudaEventCreateWithFlags(&evFork, cudaEventDisableTiming);
        cudaEventCreateWithFlags(&evJoin, cudaEventDisableTiming);
    }

    // ---- fork: layer-1 GEMM on s2 (depends only on x, W1) ----
    cudaEventRecord(evFork, 0);
    cudaStreamWaitEvent(s2, evFork, 0);
    wgemm_kernel<128, 128, false><<<(n + 127) / 128, 512, SM1, s2>>>(x, W1, T, n);
    cudaEventRecord(evJoin, s2);

    // ---- preprocessing chain on the capture stream (5 kernels) ----
    k_pre0<<<(NN + 255) / 256, 256>>>(ei);
    k_count_deg<<<(EE + 255) / 256, 256>>>(ei);
    k_dinv_scan<<<NB, SCAN_B>>>();
    k_scan_bsum_par<<<1, 256>>>();
    k_build_csr<<<(EE + 255) / 256, 256>>>(ei);

    // ---- join: gather1 needs both gemm1 (T) and the CSR ----
    cudaStreamWaitEvent(0, evJoin, 0);
    gather_kernel<128><<<(n * 16 + 255) / 256, 256>>>(b1, Oh, n);

    // --- layer 2: 128 -> 64 ---
    wgemm_kernel<128, 64, true><<<(n + 127) / 128, 512, SM2>>>(Oh, W2, T, n);
    gather_kernel<64><<<(n * 8 + 255) / 256, 256>>>(b2, Oh, n);

    // --- layer 3: 64 -> 32 + head ---
    wgemm_kernel<64, 32, true><<<(n + 127) / 128, 512, SM3>>>(Oh, W3, T, n);
    gather_head_kernel<<<(n * 4 + 255) / 256, 256>>>(b3, Wl, bl, out, n);
}